// round 11
// baseline (speedup 1.0000x reference)
#include <cuda_runtime.h>

#define HEADS 8
#define D 256
#define NCAP 32768
#define MCAP 327680

// Segment-sum scratch, packed: seg[(node*b + bb)*HEADS + h]. 2MB slack.
__device__ float g_seg[1 << 19];

// counting-sort / CSR scratch
__device__ int  g_cnt[NCAP];    // histogram; starts zero, re-zeroed by scan each call
__device__ int  g_ofs[NCAP + 1];// CSR row start + sentinel
__device__ int  g_cur[NCAP];    // scatter cursor (mutated)
__device__ int2 g_edges[MCAP];  // {ki, original_edge_idx} grouped by q-node

// Zero seg; histogram e0. (g_cnt is zero on entry: static zero-init on the
// first call, re-zeroed by scan_kernel on every call.)
__global__ void __launch_bounds__(256) prep_kernel(
    const int* __restrict__ e0, int m, int segcount)
{
    int i = blockIdx.x * blockDim.x + threadIdx.x;
    int stride = gridDim.x * blockDim.x;

    for (int s = i; s < segcount; s += stride) g_seg[s] = 0.0f;
    for (int j = i; j < m; j += stride) atomicAdd(&g_cnt[e0[j]], 1);
}

// Single-block exclusive scan of g_cnt[0..n) -> g_ofs,g_cur; re-zeroes g_cnt.
__global__ void __launch_bounds__(1024) scan_kernel(int n)
{
    __shared__ int warpsum[32];
    __shared__ int warpexcl[32];
    __shared__ int carry;
    int tid = threadIdx.x, lane = tid & 31, wid = tid >> 5;
    if (tid == 0) carry = 0;
    __syncthreads();

    for (int base = 0; base < n; base += 1024) {
        int i = base + tid;
        int v = (i < n) ? g_cnt[i] : 0;
        if (i < n) g_cnt[i] = 0;           // reset for next call's histogram
        int s = v;
        #pragma unroll
        for (int off = 1; off < 32; off <<= 1) {
            int t = __shfl_up_sync(0xffffffffu, s, off);
            if (lane >= off) s += t;
        }
        if (lane == 31) warpsum[wid] = s;
        __syncthreads();
        if (wid == 0) {
            int w = warpsum[lane];
            int ws = w;
            #pragma unroll
            for (int off = 1; off < 32; off <<= 1) {
                int t = __shfl_up_sync(0xffffffffu, ws, off);
                if (lane >= off) ws += t;
            }
            warpexcl[lane] = ws - w;
        }
        __syncthreads();
        int excl = (s - v) + warpexcl[wid] + carry;
        if (i < n) { g_ofs[i] = excl; g_cur[i] = excl; }
        __syncthreads();
        if (tid == 0) carry += warpexcl[31] + warpsum[31];
        __syncthreads();
    }
    if (threadIdx.x == 0) g_ofs[n] = carry;   // sentinel
}

// Scatter edges into q-node-grouped order: {ki, edge_idx}. 4 edges per
// thread with vectorized index loads -> 4 atomic/store chains in flight.
__global__ void __launch_bounds__(256) scatter_kernel(
    const int* __restrict__ e0, const int* __restrict__ e1, int m)
{
    int t = blockIdx.x * blockDim.x + threadIdx.x;
    int j0 = t * 4;
    if (j0 >= m) return;

    if (j0 + 4 <= m) {
        int4 q4 = *(const int4*)(e0 + j0);
        int4 k4 = *(const int4*)(e1 + j0);
        int p0 = atomicAdd(&g_cur[q4.x], 1);
        int p1 = atomicAdd(&g_cur[q4.y], 1);
        int p2 = atomicAdd(&g_cur[q4.z], 1);
        int p3 = atomicAdd(&g_cur[q4.w], 1);
        g_edges[p0] = make_int2(k4.x, j0 + 0);
        g_edges[p1] = make_int2(k4.y, j0 + 1);
        g_edges[p2] = make_int2(k4.z, j0 + 2);
        g_edges[p3] = make_int2(k4.w, j0 + 3);
    } else {
        for (int j = j0; j < m; j++) {
            int pos = atomicAdd(&g_cur[e0[j]], 1);
            g_edges[pos] = make_int2(e1[j], j);
        }
    }
}

__device__ __forceinline__ float dot8(float4 a0, float4 a1, float4 c0, float4 c1) {
    return a0.x * c0.x + a0.y * c0.y + a0.z * c0.z + a0.w * c0.w
         + a1.x * c1.x + a1.y * c1.y + a1.z * c1.z + a1.w * c1.w;
}

// A1: one warp per q-node, all fp32 straight from the inputs. q row (both
// batches) loaded once into registers; loop over the node's edges loads k
// rows (2x float4 per batch) with a 1-deep edge-record prefetch. No atomics.
__global__ void __launch_bounds__(256) passA1_kernel(
    const float4* __restrict__ q, const float4* __restrict__ k,
    float* __restrict__ ex_out, int n, int m, int b)
{
    int v = blockIdx.x * (blockDim.x >> 5) + (threadIdx.x >> 5);
    int lane = threadIdx.x & 31;
    if (v >= n) return;

    int start = g_ofs[v];
    int cnt = g_ofs[v + 1] - start;
    if (cnt == 0) return;

    long long row = (long long)v * (D / 4) + lane * 2;
    long long bstride = (long long)n * (D / 4);

    if (b == 2) {
        float4 qa0 = q[row],            qb0 = q[row + 1];
        float4 qa1 = q[row + bstride],  qb1 = q[row + bstride + 1];

        int2 ed = g_edges[start];
        for (int t = 0; t < cnt; t++) {
            int ki = ed.x, j = ed.y;
            long long rowk = (long long)ki * (D / 4) + lane * 2;
            float4 ka0 = k[rowk];
            float4 kb0 = k[rowk + 1];
            float4 ka1 = k[rowk + bstride];
            float4 kb1 = k[rowk + bstride + 1];
            if (t + 1 < cnt) ed = g_edges[start + t + 1];

            float s0 = dot8(qa0, qb0, ka0, kb0);
            float s1 = dot8(qa1, qb1, ka1, kb1);
            s0 += __shfl_xor_sync(0xffffffffu, s0, 1);
            s1 += __shfl_xor_sync(0xffffffffu, s1, 1);
            s0 += __shfl_xor_sync(0xffffffffu, s0, 2);
            s1 += __shfl_xor_sync(0xffffffffu, s1, 2);

            // a = dot/sqrt(256); global max-shift dropped (ratio is
            // shift-invariant, exp(a) <= ~8, eps below fp32 ulp of denom).
            float ex0 = __expf(s0 * 0.0625f);
            float ex1 = __expf(s1 * 0.0625f);

            if ((lane & 3) == 0) {
                int h = lane >> 2;
                ex_out[(((long long)j) << 3) + h] = ex0;
                ex_out[(((long long)(m + j)) << 3) + h] = ex1;
            }
        }
    } else {
        for (int t = 0; t < cnt; t++) {
            int2 ed = g_edges[start + t];
            long long rowk = (long long)ed.x * (D / 4) + lane * 2;
            for (int bb = 0; bb < b; bb++) {
                float4 qa = q[row + bb * bstride];
                float4 qb = q[row + bb * bstride + 1];
                float4 ka = k[rowk + bb * bstride];
                float4 kb = k[rowk + bb * bstride + 1];
                float s = dot8(qa, qb, ka, kb);
                s += __shfl_xor_sync(0xffffffffu, s, 1);
                s += __shfl_xor_sync(0xffffffffu, s, 2);
                float ex = __expf(s * 0.0625f);
                if ((lane & 3) == 0)
                    ex_out[(((long long)bb * m + ed.y) << 3) + (lane >> 2)] = ex;
            }
        }
    }
}

// A2: pure segment reduction. One thread per 16B ex chunk: stream-read ex,
// one red.global.add.v4.f32 into the packed seg table.
__global__ void __launch_bounds__(256) passA2_kernel(
    const int* __restrict__ r, const float4* __restrict__ ex,
    int m, int b)
{
    int tid = blockIdx.x * blockDim.x + threadIdx.x;
    int total = m * b * 2;
    if (tid >= total) return;
    int bb = tid / (2 * m);
    int rem = tid - bb * 2 * m;
    int mm = rem >> 1;
    int half = rem & 1;
    int rr = r[mm];

    float4 v = ex[tid];

    float* segp = &g_seg[(((long long)rr * b + bb) << 3) + (half << 2)];
    asm volatile("red.global.add.v4.f32 [%0], {%1, %2, %3, %4};"
                 :: "l"(segp), "f"(v.x), "f"(v.y), "f"(v.z), "f"(v.w)
                 : "memory");
}

// B: one thread per (batch, edge): normalize 8 heads.
__global__ void __launch_bounds__(256) passB_kernel(
    const int* __restrict__ r, float* __restrict__ out, int m, int b)
{
    int i = blockIdx.x * blockDim.x + threadIdx.x;
    if (i >= m * b) return;
    int bb = i / m;
    int mm = i - bb * m;
    int rr = r[mm];

    const float4* segp = (const float4*)&g_seg[(((long long)rr * b + bb) << 3)];
    float4 s0 = segp[0], s1 = segp[1];

    float4* op = (float4*)(out + ((long long)i << 3));
    float4 v0 = op[0], v1 = op[1];

    v0.x /= (s0.x + 1e-16f); v0.y /= (s0.y + 1e-16f);
    v0.z /= (s0.z + 1e-16f); v0.w /= (s0.w + 1e-16f);
    v1.x /= (s1.x + 1e-16f); v1.y /= (s1.y + 1e-16f);
    v1.z /= (s1.z + 1e-16f); v1.w /= (s1.w + 1e-16f);

    op[0] = v0; op[1] = v1;
}

extern "C" void kernel_launch(void* const* d_in, const int* in_sizes, int n_in,
                              void* d_out, int out_size) {
    const float* q = (const float*)d_in[0];
    const float* k = (const float*)d_in[1];
    const int*   e = (const int*)d_in[2];
    const int*   r = (const int*)d_in[3];
    float* out = (float*)d_out;

    int m = in_sizes[3];                    // r has m elements
    int b = out_size / (m * HEADS);         // output is (b, m, HEADS)
    int n = in_sizes[0] / (b * D);          // q is (b, n, D)

    const int* e0 = e;
    const int* e1 = e + m;

    int seg_count = n * b * HEADS;
    prep_kernel<<<1200, 256>>>(e0, m, seg_count);

    scan_kernel<<<1, 1024>>>(n);
    scatter_kernel<<<((m + 3) / 4 + 255) / 256, 256>>>(e0, e1, m);

    int warps = n;                          // one warp per q-node
    passA1_kernel<<<(warps + 7) / 8, 256>>>((const float4*)q, (const float4*)k,
                                            out, n, m, b);

    int mb = m * b;
    int chunks = mb * 2;
    passA2_kernel<<<(chunks + 255) / 256, 256>>>(r, (const float4*)out, m, b);

    passB_kernel<<<(mb + 255) / 256, 256>>>(r, out, m, b);
}

// round 12
// speedup vs baseline: 1.2173x; 1.2173x over previous
#include <cuda_runtime.h>
#include <cuda_fp16.h>

#define HEADS 8
#define D 256
#define NCAP 32768
#define MCAP 327680

// Segment-sum scratch, packed: seg[(node*b + bb)*HEADS + h]. 2MB slack.
__device__ float g_seg[1 << 19];

// fp16 mirror of k only (q is read fp32, register-cached per node).
#define K_CAP 10485760
__device__ __half g_kh[K_CAP];

// counting-sort / CSR scratch (16B aligned for int4 access)
__device__ __align__(16) int  g_cnt[NCAP];     // zeroed by scan each call
__device__ __align__(16) int  g_ofs[NCAP + 4]; // CSR row start + sentinel
__device__ __align__(16) int  g_cur[NCAP];     // scatter cursor
__device__ int4 g_edges[MCAP];                 // {ki, edge_idx, r, 0} grouped by q-node

// Zero seg; histogram e0; convert k -> fp16.
__global__ void __launch_bounds__(256) prep_kernel(
    const float4* __restrict__ k,
    const int* __restrict__ e0, int m, int n16, int segcount)
{
    int i = blockIdx.x * blockDim.x + threadIdx.x;
    int stride = gridDim.x * blockDim.x;

    for (int s = i; s < segcount; s += stride) g_seg[s] = 0.0f;
    for (int j = i; j < m; j += stride) atomicAdd(&g_cnt[e0[j]], 1);

    uint4* kh = (uint4*)g_kh;
    for (int j = i; j < n16; j += stride) {
        float4 v0 = k[2 * j], v1 = k[2 * j + 1];
        __half2 h0 = __floats2half2_rn(v0.x, v0.y);
        __half2 h1 = __floats2half2_rn(v0.z, v0.w);
        __half2 h2 = __floats2half2_rn(v1.x, v1.y);
        __half2 h3 = __floats2half2_rn(v1.z, v1.w);
        uint4 u;
        u.x = *(unsigned*)&h0; u.y = *(unsigned*)&h1;
        u.z = *(unsigned*)&h2; u.w = *(unsigned*)&h3;
        kh[j] = u;
    }
}

// Single-block exclusive scan, 4 elements/thread (int4), 5 tiles for n=20k.
// Re-zeroes g_cnt. g_cnt entries >= n are always zero (padding).
__global__ void __launch_bounds__(1024) scan_kernel(int n)
{
    __shared__ int wsum[32];
    __shared__ int wexcl[32];
    __shared__ int s_carry;
    int tid = threadIdx.x, lane = tid & 31, wid = tid >> 5;
    if (tid == 0) s_carry = 0;
    __syncthreads();

    int nt = (n + 4095) >> 12;
    for (int tb = 0; tb < nt; tb++) {
        int i4 = (tb << 12) + (tid << 2);
        int4 c = *(const int4*)&g_cnt[i4];
        *(int4*)&g_cnt[i4] = make_int4(0, 0, 0, 0);  // reset for next call
        int lsum = c.x + c.y + c.z + c.w;
        int s = lsum;
        #pragma unroll
        for (int off = 1; off < 32; off <<= 1) {
            int t = __shfl_up_sync(0xffffffffu, s, off);
            if (lane >= off) s += t;
        }
        if (lane == 31) wsum[wid] = s;
        __syncthreads();
        if (wid == 0) {
            int w = wsum[lane];
            int ws = w;
            #pragma unroll
            for (int off = 1; off < 32; off <<= 1) {
                int t = __shfl_up_sync(0xffffffffu, ws, off);
                if (lane >= off) ws += t;
            }
            wexcl[lane] = ws - w;
        }
        __syncthreads();
        int excl = (s - lsum) + wexcl[wid] + s_carry;
        int o0 = excl, o1 = o0 + c.x, o2 = o1 + c.y, o3 = o2 + c.z;
        *(int4*)&g_ofs[i4] = make_int4(o0, o1, o2, o3);
        *(int4*)&g_cur[i4] = make_int4(o0, o1, o2, o3);
        __syncthreads();                       // all threads have read s_carry
        if (tid == 1023) s_carry = excl + lsum; // += tile total
        __syncthreads();
    }
    if (tid == 0) g_ofs[n] = s_carry;          // sentinel
}

// Scatter edges into q-node-grouped order: {ki, edge_idx, r}. 4 edges per
// thread with vectorized index loads -> 4 atomic/store chains in flight.
__global__ void __launch_bounds__(256) scatter_kernel(
    const int* __restrict__ e0, const int* __restrict__ e1,
    const int* __restrict__ r, int m)
{
    int t = blockIdx.x * blockDim.x + threadIdx.x;
    int j0 = t * 4;
    if (j0 >= m) return;

    if (j0 + 4 <= m) {
        int4 q4 = *(const int4*)(e0 + j0);
        int4 k4 = *(const int4*)(e1 + j0);
        int4 r4 = *(const int4*)(r + j0);
        int p0 = atomicAdd(&g_cur[q4.x], 1);
        int p1 = atomicAdd(&g_cur[q4.y], 1);
        int p2 = atomicAdd(&g_cur[q4.z], 1);
        int p3 = atomicAdd(&g_cur[q4.w], 1);
        g_edges[p0] = make_int4(k4.x, j0 + 0, r4.x, 0);
        g_edges[p1] = make_int4(k4.y, j0 + 1, r4.y, 0);
        g_edges[p2] = make_int4(k4.z, j0 + 2, r4.z, 0);
        g_edges[p3] = make_int4(k4.w, j0 + 3, r4.w, 0);
    } else {
        for (int j = j0; j < m; j++) {
            int pos = atomicAdd(&g_cur[e0[j]], 1);
            g_edges[pos] = make_int4(e1[j], j, r[j], 0);
        }
    }
}

// mixed dot: 8 fp32 q elements (2 float4) x 8 fp16 k elements (uint4)
__device__ __forceinline__ float dotqk(float4 qa, float4 qb, uint4 uk) {
    float s = 0.0f;
    float2 c;
    c = __half22float2(*(const __half2*)&uk.x); s += qa.x * c.x + qa.y * c.y;
    c = __half22float2(*(const __half2*)&uk.y); s += qa.z * c.x + qa.w * c.y;
    c = __half22float2(*(const __half2*)&uk.z); s += qb.x * c.x + qb.y * c.y;
    c = __half22float2(*(const __half2*)&uk.w); s += qb.z * c.x + qb.w * c.y;
    return s;
}

// A1: one warp per q-node. q row (both batches, fp32) in registers; loop over
// edges loads fp16 k rows with a 1-deep edge prefetch. Epilogue stores ex and
// issues the segment RED directly (no separate reduction pass).
__global__ void __launch_bounds__(256) passA1_kernel(
    const float4* __restrict__ q,
    float* __restrict__ ex_out, int n, int m, int b)
{
    int v = blockIdx.x * (blockDim.x >> 5) + (threadIdx.x >> 5);
    int lane = threadIdx.x & 31;
    if (v >= n) return;

    int start = g_ofs[v];
    int cnt = g_ofs[v + 1] - start;
    if (cnt == 0) return;

    const uint4* kbase = (const uint4*)g_kh;
    long long kbstride = (long long)n * (D / 8);
    long long qrow = (long long)v * (D / 4) + lane * 2;
    long long qbstride = (long long)n * (D / 4);

    if (b == 2) {
        float4 qa0 = q[qrow],            qb0 = q[qrow + 1];
        float4 qa1 = q[qrow + qbstride], qb1 = q[qrow + qbstride + 1];

        int4 ed = g_edges[start];
        for (int t = 0; t < cnt; t++) {
            int ki = ed.x, j = ed.y, rr = ed.z;
            long long rowk = (long long)ki * (D / 8) + lane;
            uint4 uk0 = kbase[rowk];
            uint4 uk1 = kbase[rowk + kbstride];
            if (t + 1 < cnt) ed = g_edges[start + t + 1];

            float s0 = dotqk(qa0, qb0, uk0);
            float s1 = dotqk(qa1, qb1, uk1);
            s0 += __shfl_xor_sync(0xffffffffu, s0, 1);
            s1 += __shfl_xor_sync(0xffffffffu, s1, 1);
            s0 += __shfl_xor_sync(0xffffffffu, s0, 2);
            s1 += __shfl_xor_sync(0xffffffffu, s1, 2);

            // a = dot/sqrt(256); global max-shift dropped (ratio is
            // shift-invariant, exp(a) <= ~8, eps below fp32 ulp of denom).
            float ex0 = __expf(s0 * 0.0625f);
            float ex1 = __expf(s1 * 0.0625f);

            if ((lane & 3) == 0) {
                int h = lane >> 2;
                ex_out[(((long long)j) << 3) + h] = ex0;
                ex_out[(((long long)(m + j)) << 3) + h] = ex1;
                // packed seg: (rr*2+bb)*8 + h ; 8 lanes -> one 32B RED sector
                atomicAdd(&g_seg[(rr << 4) + h], ex0);
                atomicAdd(&g_seg[(rr << 4) + 8 + h], ex1);
            }
        }
    } else {
        for (int t = 0; t < cnt; t++) {
            int4 ed = g_edges[start + t];
            long long rowk = (long long)ed.x * (D / 8) + lane;
            for (int bb = 0; bb < b; bb++) {
                float4 qa = q[qrow + bb * qbstride];
                float4 qb = q[qrow + bb * qbstride + 1];
                uint4 uk = kbase[rowk + bb * kbstride];
                float s = dotqk(qa, qb, uk);
                s += __shfl_xor_sync(0xffffffffu, s, 1);
                s += __shfl_xor_sync(0xffffffffu, s, 2);
                float ex = __expf(s * 0.0625f);
                if ((lane & 3) == 0) {
                    int h = lane >> 2;
                    ex_out[(((long long)bb * m + ed.y) << 3) + h] = ex;
                    atomicAdd(&g_seg[(((long long)ed.z * b + bb) << 3) + h], ex);
                }
            }
        }
    }
}

// B: one thread per (batch, edge): normalize 8 heads.
__global__ void __launch_bounds__(256) passB_kernel(
    const int* __restrict__ r, float* __restrict__ out, int m, int b)
{
    int i = blockIdx.x * blockDim.x + threadIdx.x;
    if (i >= m * b) return;
    int bb = i / m;
    int mm = i - bb * m;
    int rr = r[mm];

    const float4* segp = (const float4*)&g_seg[(((long long)rr * b + bb) << 3)];
    float4 s0 = segp[0], s1 = segp[1];

    float4* op = (float4*)(out + ((long long)i << 3));
    float4 v0 = op[0], v1 = op[1];

    v0.x /= (s0.x + 1e-16f); v0.y /= (s0.y + 1e-16f);
    v0.z /= (s0.z + 1e-16f); v0.w /= (s0.w + 1e-16f);
    v1.x /= (s1.x + 1e-16f); v1.y /= (s1.y + 1e-16f);
    v1.z /= (s1.z + 1e-16f); v1.w /= (s1.w + 1e-16f);

    op[0] = v0; op[1] = v1;
}

extern "C" void kernel_launch(void* const* d_in, const int* in_sizes, int n_in,
                              void* d_out, int out_size) {
    const float* q = (const float*)d_in[0];
    const float* k = (const float*)d_in[1];
    const int*   e = (const int*)d_in[2];
    const int*   r = (const int*)d_in[3];
    float* out = (float*)d_out;

    int m = in_sizes[3];                    // r has m elements
    int b = out_size / (m * HEADS);         // output is (b, m, HEADS)
    int n = in_sizes[0] / (b * D);          // q is (b, n, D)

    const int* e0 = e;
    const int* e1 = e + m;

    int seg_count = n * b * HEADS;
    int n16 = (b * n * D) / 8;              // 16-byte half chunks of k
    prep_kernel<<<4000, 256>>>((const float4*)k, e0, m, n16, seg_count);

    scan_kernel<<<1, 1024>>>(n);
    scatter_kernel<<<((m + 3) / 4 + 255) / 256, 256>>>(e0, e1, r, m);

    int warps = n;                          // one warp per q-node
    passA1_kernel<<<(warps + 7) / 8, 256>>>((const float4*)q, out, n, m, b);

    int mb = m * b;
    passB_kernel<<<(mb + 255) / 256, 256>>>(r, out, m, b);
}

// round 13
// speedup vs baseline: 1.2985x; 1.0667x over previous
#include <cuda_runtime.h>
#include <cuda_fp16.h>

#define HEADS 8
#define D 256
#define NCAP 32768
#define MCAP 327680

// Segment-sum scratch, packed: seg[(node*b + bb)*HEADS + h]. 2MB slack.
__device__ float g_seg[1 << 19];

// fp16 mirror of k only (q is read fp32, register-cached per node).
#define K_CAP 10485760
__device__ __half g_kh[K_CAP];

// counting-sort / CSR scratch (16B aligned for int4 access)
__device__ __align__(16) int  g_cnt[NCAP];     // zeroed by scan each call
__device__ __align__(16) int  g_ofs[NCAP + 4]; // CSR row start + sentinel
__device__ __align__(16) int  g_cur[NCAP];     // scatter cursor
// {k_byteoff, ex_byteoff, seg_byteoff, 0} grouped by q-node
__device__ int4 g_edges[MCAP];

// Zero seg; histogram e0; convert k -> fp16.
__global__ void __launch_bounds__(256) prep_kernel(
    const float4* __restrict__ k,
    const int* __restrict__ e0, int m, int n16, int segcount)
{
    int i = blockIdx.x * blockDim.x + threadIdx.x;
    int stride = gridDim.x * blockDim.x;

    for (int s = i; s < segcount; s += stride) g_seg[s] = 0.0f;
    for (int j = i; j < m; j += stride) atomicAdd(&g_cnt[e0[j]], 1);

    uint4* kh = (uint4*)g_kh;
    for (int j = i; j < n16; j += stride) {
        float4 v0 = k[2 * j], v1 = k[2 * j + 1];
        __half2 h0 = __floats2half2_rn(v0.x, v0.y);
        __half2 h1 = __floats2half2_rn(v0.z, v0.w);
        __half2 h2 = __floats2half2_rn(v1.x, v1.y);
        __half2 h3 = __floats2half2_rn(v1.z, v1.w);
        uint4 u;
        u.x = *(unsigned*)&h0; u.y = *(unsigned*)&h1;
        u.z = *(unsigned*)&h2; u.w = *(unsigned*)&h3;
        kh[j] = u;
    }
}

// Single-block exclusive scan, 4 elements/thread (int4). Re-zeroes g_cnt.
__global__ void __launch_bounds__(1024) scan_kernel(int n)
{
    __shared__ int wsum[32];
    __shared__ int wexcl[32];
    __shared__ int s_carry;
    int tid = threadIdx.x, lane = tid & 31, wid = tid >> 5;
    if (tid == 0) s_carry = 0;
    __syncthreads();

    int nt = (n + 4095) >> 12;
    for (int tb = 0; tb < nt; tb++) {
        int i4 = (tb << 12) + (tid << 2);
        int4 c = *(const int4*)&g_cnt[i4];
        *(int4*)&g_cnt[i4] = make_int4(0, 0, 0, 0);  // reset for next call
        int lsum = c.x + c.y + c.z + c.w;
        int s = lsum;
        #pragma unroll
        for (int off = 1; off < 32; off <<= 1) {
            int t = __shfl_up_sync(0xffffffffu, s, off);
            if (lane >= off) s += t;
        }
        if (lane == 31) wsum[wid] = s;
        __syncthreads();
        if (wid == 0) {
            int w = wsum[lane];
            int ws = w;
            #pragma unroll
            for (int off = 1; off < 32; off <<= 1) {
                int t = __shfl_up_sync(0xffffffffu, ws, off);
                if (lane >= off) ws += t;
            }
            wexcl[lane] = ws - w;
        }
        __syncthreads();
        int excl = (s - lsum) + wexcl[wid] + s_carry;
        int o0 = excl, o1 = o0 + c.x, o2 = o1 + c.y, o3 = o2 + c.z;
        *(int4*)&g_ofs[i4] = make_int4(o0, o1, o2, o3);
        *(int4*)&g_cur[i4] = make_int4(o0, o1, o2, o3);
        __syncthreads();
        if (tid == 1023) s_carry = excl + lsum;
        __syncthreads();
    }
    if (tid == 0) g_ofs[n] = s_carry;          // sentinel
}

// Scatter edges grouped by q-node, storing PRECOMPUTED BYTE OFFSETS:
//   k_off  = ki * 512        (k row: 256 halves = 512 B)
//   ex_off = j * 32          (ex row: 8 floats = 32 B, batch 0)
//   seg_off= rr * b * 32     (seg row: b*8 floats)
__global__ void __launch_bounds__(256) scatter_kernel(
    const int* __restrict__ e0, const int* __restrict__ e1,
    const int* __restrict__ r, int m, int b)
{
    int t = blockIdx.x * blockDim.x + threadIdx.x;
    int j0 = t * 4;
    if (j0 >= m) return;

    if (j0 + 4 <= m) {
        int4 q4 = *(const int4*)(e0 + j0);
        int4 k4 = *(const int4*)(e1 + j0);
        int4 r4 = *(const int4*)(r + j0);
        int p0 = atomicAdd(&g_cur[q4.x], 1);
        int p1 = atomicAdd(&g_cur[q4.y], 1);
        int p2 = atomicAdd(&g_cur[q4.z], 1);
        int p3 = atomicAdd(&g_cur[q4.w], 1);
        int b32 = b * 32;
        g_edges[p0] = make_int4(k4.x << 9, (j0 + 0) << 5, r4.x * b32, 0);
        g_edges[p1] = make_int4(k4.y << 9, (j0 + 1) << 5, r4.y * b32, 0);
        g_edges[p2] = make_int4(k4.z << 9, (j0 + 2) << 5, r4.z * b32, 0);
        g_edges[p3] = make_int4(k4.w << 9, (j0 + 3) << 5, r4.w * b32, 0);
    } else {
        for (int j = j0; j < m; j++) {
            int pos = atomicAdd(&g_cur[e0[j]], 1);
            g_edges[pos] = make_int4(e1[j] << 9, j << 5, r[j] * b * 32, 0);
        }
    }
}

// mixed dot: 8 fp32 q elements (2 float4) x 8 fp16 k elements (uint4)
__device__ __forceinline__ float dotqk(float4 qa, float4 qb, uint4 uk) {
    float s = 0.0f;
    float2 c;
    c = __half22float2(*(const __half2*)&uk.x); s += qa.x * c.x + qa.y * c.y;
    c = __half22float2(*(const __half2*)&uk.y); s += qa.z * c.x + qa.w * c.y;
    c = __half22float2(*(const __half2*)&uk.z); s += qb.x * c.x + qb.y * c.y;
    c = __half22float2(*(const __half2*)&uk.w); s += qb.z * c.x + qb.w * c.y;
    return s;
}

// A1: one warp per q-node. q row (both batches, fp32) in registers; edge loop
// uses precomputed 32-bit byte offsets -> no index multiplies in the hot loop.
// Epilogue stores ex and issues segment REDs directly.
__global__ void __launch_bounds__(256) passA1_kernel(
    const float4* __restrict__ q,
    float* __restrict__ ex_out, int n, int m, int b)
{
    int v = blockIdx.x * (blockDim.x >> 5) + (threadIdx.x >> 5);
    int lane = threadIdx.x & 31;
    if (v >= n) return;

    int start = g_ofs[v];
    int cnt = g_ofs[v + 1] - start;
    if (cnt == 0) return;

    const char* kb = (const char*)g_kh;
    char* exb = (char*)ex_out;
    char* segb = (char*)g_seg;
    int lane16 = lane * 16;
    int kbstride = n << 9;               // bytes between batches in g_kh

    if (b == 2) {
        long long qrow = (long long)v * (D / 4) + lane * 2;
        long long qbs = (long long)n * (D / 4);
        float4 qa0 = q[qrow],       qb0 = q[qrow + 1];
        float4 qa1 = q[qrow + qbs], qb1 = q[qrow + qbs + 1];

        bool wr = (lane & 3) == 0;
        int h4 = lane & 28;               // (lane>>2)*4 = head byte offset
        int exb1 = m << 5;                // batch-1 ex byte offset

        int4 ed = g_edges[start];
        for (int t = 0; t < cnt; t++) {
            int koff = ed.x + lane16;
            int exoff = ed.y, soff = ed.z;
            uint4 uk0 = *(const uint4*)(kb + koff);
            uint4 uk1 = *(const uint4*)(kb + koff + kbstride);
            if (t + 1 < cnt) ed = g_edges[start + t + 1];

            float s0 = dotqk(qa0, qb0, uk0);
            float s1 = dotqk(qa1, qb1, uk1);
            s0 += __shfl_xor_sync(0xffffffffu, s0, 1);
            s1 += __shfl_xor_sync(0xffffffffu, s1, 1);
            s0 += __shfl_xor_sync(0xffffffffu, s0, 2);
            s1 += __shfl_xor_sync(0xffffffffu, s1, 2);

            // a = dot/sqrt(256); global max-shift dropped (ratio is
            // shift-invariant, exp(a) <= ~8, eps below fp32 ulp of denom).
            float ex0 = __expf(s0 * 0.0625f);
            float ex1 = __expf(s1 * 0.0625f);

            if (wr) {
                *(float*)(exb + exoff + h4) = ex0;
                *(float*)(exb + exoff + exb1 + h4) = ex1;
                atomicAdd((float*)(segb + soff + h4), ex0);
                atomicAdd((float*)(segb + soff + 32 + h4), ex1);
            }
        }
    } else {
        bool wr = (lane & 3) == 0;
        int h4 = lane & 28;
        long long qrow = (long long)v * (D / 4) + lane * 2;
        long long qbs = (long long)n * (D / 4);
        for (int t = 0; t < cnt; t++) {
            int4 ed = g_edges[start + t];
            for (int bb = 0; bb < b; bb++) {
                float4 qa = q[qrow + bb * qbs];
                float4 qb = q[qrow + bb * qbs + 1];
                uint4 uk = *(const uint4*)(kb + ed.x + lane16 + bb * kbstride);
                float s = dotqk(qa, qb, uk);
                s += __shfl_xor_sync(0xffffffffu, s, 1);
                s += __shfl_xor_sync(0xffffffffu, s, 2);
                float ex = __expf(s * 0.0625f);
                if (wr) {
                    *(float*)(exb + ed.y + (long long)bb * (m << 5) + h4) = ex;
                    atomicAdd((float*)(segb + ed.z + bb * 32 + h4), ex);
                }
            }
        }
    }
}

// B: one thread per (batch, edge): normalize 8 heads.
__global__ void __launch_bounds__(256) passB_kernel(
    const int* __restrict__ r, float* __restrict__ out, int m, int b)
{
    int i = blockIdx.x * blockDim.x + threadIdx.x;
    if (i >= m * b) return;
    int bb = i / m;
    int mm = i - bb * m;
    int rr = r[mm];

    const float4* segp = (const float4*)&g_seg[(((long long)rr * b + bb) << 3)];
    float4 s0 = segp[0], s1 = segp[1];

    float4* op = (float4*)(out + ((long long)i << 3));
    float4 v0 = op[0], v1 = op[1];

    v0.x /= (s0.x + 1e-16f); v0.y /= (s0.y + 1e-16f);
    v0.z /= (s0.z + 1e-16f); v0.w /= (s0.w + 1e-16f);
    v1.x /= (s1.x + 1e-16f); v1.y /= (s1.y + 1e-16f);
    v1.z /= (s1.z + 1e-16f); v1.w /= (s1.w + 1e-16f);

    op[0] = v0; op[1] = v1;
}

extern "C" void kernel_launch(void* const* d_in, const int* in_sizes, int n_in,
                              void* d_out, int out_size) {
    const float* q = (const float*)d_in[0];
    const float* k = (const float*)d_in[1];
    const int*   e = (const int*)d_in[2];
    const int*   r = (const int*)d_in[3];
    float* out = (float*)d_out;

    int m = in_sizes[3];                    // r has m elements
    int b = out_size / (m * HEADS);         // output is (b, m, HEADS)
    int n = in_sizes[0] / (b * D);          // q is (b, n, D)

    const int* e0 = e;
    const int* e1 = e + m;

    int seg_count = n * b * HEADS;
    int n16 = (b * n * D) / 8;              // 16-byte half chunks of k
    prep_kernel<<<4000, 256>>>((const float4*)k, e0, m, n16, seg_count);

    scan_kernel<<<1, 1024>>>(n);
    scatter_kernel<<<((m + 3) / 4 + 255) / 256, 256>>>(e0, e1, r, m, b);

    int warps = n;                          // one warp per q-node
    passA1_kernel<<<(warps + 7) / 8, 256>>>((const float4*)q, out, n, m, b);

    int mb = m * b;
    passB_kernel<<<(mb + 255) / 256, 256>>>(r, out, m, b);
}

// round 14
// speedup vs baseline: 1.3033x; 1.0037x over previous
#include <cuda_runtime.h>
#include <cuda_fp16.h>

#define HEADS 8
#define D 256
#define NCAP 32768
#define MCAP 327680

// Segment-sum scratch, packed: seg[(node*b + bb)*HEADS + h]. 2MB slack.
__device__ float g_seg[1 << 19];

// fp16 mirror of k only (q converted to half2 registers per node).
#define K_CAP 10485760
__device__ __half g_kh[K_CAP];

// counting-sort / CSR scratch (16B aligned for int4 access)
__device__ __align__(16) int  g_cnt[NCAP];     // zeroed by scan each call
__device__ __align__(16) int  g_ofs[NCAP + 4]; // CSR row start + sentinel
__device__ __align__(16) int  g_cur[NCAP];     // scatter cursor
// {k_byteoff, ex_byteoff, seg_byteoff, 0} grouped by q-node
__device__ int4 g_edges[MCAP];

// Zero seg; histogram e0; convert k -> fp16.
__global__ void __launch_bounds__(256) prep_kernel(
    const float4* __restrict__ k,
    const int* __restrict__ e0, int m, int n16, int segcount)
{
    int i = blockIdx.x * blockDim.x + threadIdx.x;
    int stride = gridDim.x * blockDim.x;

    for (int s = i; s < segcount; s += stride) g_seg[s] = 0.0f;
    for (int j = i; j < m; j += stride) atomicAdd(&g_cnt[e0[j]], 1);

    uint4* kh = (uint4*)g_kh;
    for (int j = i; j < n16; j += stride) {
        float4 v0 = k[2 * j], v1 = k[2 * j + 1];
        __half2 h0 = __floats2half2_rn(v0.x, v0.y);
        __half2 h1 = __floats2half2_rn(v0.z, v0.w);
        __half2 h2 = __floats2half2_rn(v1.x, v1.y);
        __half2 h3 = __floats2half2_rn(v1.z, v1.w);
        uint4 u;
        u.x = *(unsigned*)&h0; u.y = *(unsigned*)&h1;
        u.z = *(unsigned*)&h2; u.w = *(unsigned*)&h3;
        kh[j] = u;
    }
}

// Single-block exclusive scan, 4 elements/thread (int4). Re-zeroes g_cnt.
__global__ void __launch_bounds__(1024) scan_kernel(int n)
{
    __shared__ int wsum[32];
    __shared__ int wexcl[32];
    __shared__ int s_carry;
    int tid = threadIdx.x, lane = tid & 31, wid = tid >> 5;
    if (tid == 0) s_carry = 0;
    __syncthreads();

    int nt = (n + 4095) >> 12;
    for (int tb = 0; tb < nt; tb++) {
        int i4 = (tb << 12) + (tid << 2);
        int4 c = *(const int4*)&g_cnt[i4];
        *(int4*)&g_cnt[i4] = make_int4(0, 0, 0, 0);  // reset for next call
        int lsum = c.x + c.y + c.z + c.w;
        int s = lsum;
        #pragma unroll
        for (int off = 1; off < 32; off <<= 1) {
            int t = __shfl_up_sync(0xffffffffu, s, off);
            if (lane >= off) s += t;
        }
        if (lane == 31) wsum[wid] = s;
        __syncthreads();
        if (wid == 0) {
            int w = wsum[lane];
            int ws = w;
            #pragma unroll
            for (int off = 1; off < 32; off <<= 1) {
                int t = __shfl_up_sync(0xffffffffu, ws, off);
                if (lane >= off) ws += t;
            }
            wexcl[lane] = ws - w;
        }
        __syncthreads();
        int excl = (s - lsum) + wexcl[wid] + s_carry;
        int o0 = excl, o1 = o0 + c.x, o2 = o1 + c.y, o3 = o2 + c.z;
        *(int4*)&g_ofs[i4] = make_int4(o0, o1, o2, o3);
        *(int4*)&g_cur[i4] = make_int4(o0, o1, o2, o3);
        __syncthreads();
        if (tid == 1023) s_carry = excl + lsum;
        __syncthreads();
    }
    if (tid == 0) g_ofs[n] = s_carry;          // sentinel
}

// Scatter edges grouped by q-node, storing precomputed byte offsets.
__global__ void __launch_bounds__(256) scatter_kernel(
    const int* __restrict__ e0, const int* __restrict__ e1,
    const int* __restrict__ r, int m, int b)
{
    int t = blockIdx.x * blockDim.x + threadIdx.x;
    int j0 = t * 4;
    if (j0 >= m) return;

    if (j0 + 4 <= m) {
        int4 q4 = *(const int4*)(e0 + j0);
        int4 k4 = *(const int4*)(e1 + j0);
        int4 r4 = *(const int4*)(r + j0);
        int p0 = atomicAdd(&g_cur[q4.x], 1);
        int p1 = atomicAdd(&g_cur[q4.y], 1);
        int p2 = atomicAdd(&g_cur[q4.z], 1);
        int p3 = atomicAdd(&g_cur[q4.w], 1);
        int b32 = b * 32;
        g_edges[p0] = make_int4(k4.x << 9, (j0 + 0) << 5, r4.x * b32, 0);
        g_edges[p1] = make_int4(k4.y << 9, (j0 + 1) << 5, r4.y * b32, 0);
        g_edges[p2] = make_int4(k4.z << 9, (j0 + 2) << 5, r4.z * b32, 0);
        g_edges[p3] = make_int4(k4.w << 9, (j0 + 3) << 5, r4.w * b32, 0);
    } else {
        for (int j = j0; j < m; j++) {
            int pos = atomicAdd(&g_cur[e0[j]], 1);
            g_edges[pos] = make_int4(e1[j] << 9, j << 5, r[j] * b * 32, 0);
        }
    }
}

// Half2 dot of 8 elements: two independent half2 accumulators (each fp16 lane
// sums only TWO products -> negligible fp16 accumulation error), fp32 fix-up.
__device__ __forceinline__ float dot8h(__half2 q0, __half2 q1, __half2 q2,
                                        __half2 q3, uint4 uk) {
    __half2 a = __hmul2(q0, *(const __half2*)&uk.x);
    a = __hfma2(q1, *(const __half2*)&uk.y, a);
    __half2 c = __hmul2(q2, *(const __half2*)&uk.z);
    c = __hfma2(q3, *(const __half2*)&uk.w, c);
    float2 fa = __half22float2(a);
    float2 fc = __half22float2(c);
    return (fa.x + fa.y) + (fc.x + fc.y);
}

// A1: one warp per q-node. q row converted to half2 registers once per node;
// edge loop: half2 dot, shfl reduce, exp, store + segment RED.
__global__ void __launch_bounds__(256) passA1_kernel(
    const float4* __restrict__ q,
    float* __restrict__ ex_out, int n, int m, int b)
{
    int v = blockIdx.x * (blockDim.x >> 5) + (threadIdx.x >> 5);
    int lane = threadIdx.x & 31;
    if (v >= n) return;

    int start = g_ofs[v];
    int cnt = g_ofs[v + 1] - start;
    if (cnt == 0) return;

    const char* kb = (const char*)g_kh;
    char* exb = (char*)ex_out;
    char* segb = (char*)g_seg;
    int lane16 = lane * 16;
    int kbstride = n << 9;               // bytes between batches in g_kh

    if (b == 2) {
        long long qrow = (long long)v * (D / 4) + lane * 2;
        long long qbs = (long long)n * (D / 4);
        float4 qa0 = q[qrow],       qb0 = q[qrow + 1];
        float4 qa1 = q[qrow + qbs], qb1 = q[qrow + qbs + 1];
        // convert q to half2 once per node (amortized over ~16 edges)
        __half2 h00 = __floats2half2_rn(qa0.x, qa0.y);
        __half2 h01 = __floats2half2_rn(qa0.z, qa0.w);
        __half2 h02 = __floats2half2_rn(qb0.x, qb0.y);
        __half2 h03 = __floats2half2_rn(qb0.z, qb0.w);
        __half2 h10 = __floats2half2_rn(qa1.x, qa1.y);
        __half2 h11 = __floats2half2_rn(qa1.z, qa1.w);
        __half2 h12 = __floats2half2_rn(qb1.x, qb1.y);
        __half2 h13 = __floats2half2_rn(qb1.z, qb1.w);

        bool wr = (lane & 3) == 0;
        int h4 = lane & 28;               // head byte offset
        int exb1 = m << 5;                // batch-1 ex byte offset

        int4 ed = g_edges[start];
        for (int t = 0; t < cnt; t++) {
            int koff = ed.x + lane16;
            int exoff = ed.y, soff = ed.z;
            uint4 uk0 = *(const uint4*)(kb + koff);
            uint4 uk1 = *(const uint4*)(kb + koff + kbstride);
            if (t + 1 < cnt) ed = g_edges[start + t + 1];

            float s0 = dot8h(h00, h01, h02, h03, uk0);
            float s1 = dot8h(h10, h11, h12, h13, uk1);
            s0 += __shfl_xor_sync(0xffffffffu, s0, 1);
            s1 += __shfl_xor_sync(0xffffffffu, s1, 1);
            s0 += __shfl_xor_sync(0xffffffffu, s0, 2);
            s1 += __shfl_xor_sync(0xffffffffu, s1, 2);

            // a = dot/sqrt(256); global max-shift dropped (ratio is
            // shift-invariant, exp(a) <= ~8, eps below fp32 ulp of denom).
            float ex0 = __expf(s0 * 0.0625f);
            float ex1 = __expf(s1 * 0.0625f);

            if (wr) {
                *(float*)(exb + exoff + h4) = ex0;
                *(float*)(exb + exoff + exb1 + h4) = ex1;
                atomicAdd((float*)(segb + soff + h4), ex0);
                atomicAdd((float*)(segb + soff + 32 + h4), ex1);
            }
        }
    } else {
        bool wr = (lane & 3) == 0;
        int h4 = lane & 28;
        long long qrow = (long long)v * (D / 4) + lane * 2;
        long long qbs = (long long)n * (D / 4);
        for (int t = 0; t < cnt; t++) {
            int4 ed = g_edges[start + t];
            for (int bb = 0; bb < b; bb++) {
                float4 qa = q[qrow + bb * qbs];
                float4 qb = q[qrow + bb * qbs + 1];
                __half2 x0 = __floats2half2_rn(qa.x, qa.y);
                __half2 x1 = __floats2half2_rn(qa.z, qa.w);
                __half2 x2 = __floats2half2_rn(qb.x, qb.y);
                __half2 x3 = __floats2half2_rn(qb.z, qb.w);
                uint4 uk = *(const uint4*)(kb + ed.x + lane16 + bb * kbstride);
                float s = dot8h(x0, x1, x2, x3, uk);
                s += __shfl_xor_sync(0xffffffffu, s, 1);
                s += __shfl_xor_sync(0xffffffffu, s, 2);
                float ex = __expf(s * 0.0625f);
                if (wr) {
                    *(float*)(exb + ed.y + (long long)bb * (m << 5) + h4) = ex;
                    atomicAdd((float*)(segb + ed.z + bb * 32 + h4), ex);
                }
            }
        }
    }
}

// B: one thread per (batch, edge): normalize 8 heads.
__global__ void __launch_bounds__(256) passB_kernel(
    const int* __restrict__ r, float* __restrict__ out, int m, int b)
{
    int i = blockIdx.x * blockDim.x + threadIdx.x;
    if (i >= m * b) return;
    int bb = i / m;
    int mm = i - bb * m;
    int rr = r[mm];

    const float4* segp = (const float4*)&g_seg[(((long long)rr * b + bb) << 3)];
    float4 s0 = segp[0], s1 = segp[1];

    float4* op = (float4*)(out + ((long long)i << 3));
    float4 v0 = op[0], v1 = op[1];

    v0.x /= (s0.x + 1e-16f); v0.y /= (s0.y + 1e-16f);
    v0.z /= (s0.z + 1e-16f); v0.w /= (s0.w + 1e-16f);
    v1.x /= (s1.x + 1e-16f); v1.y /= (s1.y + 1e-16f);
    v1.z /= (s1.z + 1e-16f); v1.w /= (s1.w + 1e-16f);

    op[0] = v0; op[1] = v1;
}

extern "C" void kernel_launch(void* const* d_in, const int* in_sizes, int n_in,
                              void* d_out, int out_size) {
    const float* q = (const float*)d_in[0];
    const float* k = (const float*)d_in[1];
    const int*   e = (const int*)d_in[2];
    const int*   r = (const int*)d_in[3];
    float* out = (float*)d_out;

    int m = in_sizes[3];                    // r has m elements
    int b = out_size / (m * HEADS);         // output is (b, m, HEADS)
    int n = in_sizes[0] / (b * D);          // q is (b, n, D)

    const int* e0 = e;
    const int* e1 = e + m;

    int seg_count = n * b * HEADS;
    int n16 = (b * n * D) / 8;              // 16-byte half chunks of k
    prep_kernel<<<4000, 256>>>((const float4*)k, e0, m, n16, seg_count);

    scan_kernel<<<1, 1024>>>(n);
    scatter_kernel<<<((m + 3) / 4 + 255) / 256, 256>>>(e0, e1, r, m, b);

    int warps = n;                          // one warp per q-node
    passA1_kernel<<<(warps + 7) / 8, 256>>>((const float4*)q, out, n, m, b);

    int mb = m * b;
    passB_kernel<<<(mb + 255) / 256, 256>>>(r, out, m, b);
}